// round 6
// baseline (speedup 1.0000x reference)
#include <cuda_runtime.h>
#include <cuda_bf16.h>

// AssociativeLIF: x (B=32, T=128, N=4096) fp32
//   i_syn[t] = 0.5 * i_syn[t-1] + x[t]
//   v[t]     = tau * v[t-1] + (1 - tau) * i_syn[t]
//   spike[t] = (v[t] >= thr) ? 1.0f : 0.0f
// tau = clip(tau_mem, 0.8, 0.98), thr = clip(v_threshold, 0.05, 0.5) per neuron.
//
// Scalar mapping (1 thread per (b,n)). Warp count is capped by problem size
// (~28 warps/SM), so latency hiding must come from MLP depth: UNROLL=16
// double-buffered keeps ~51KB/SM of loads in flight (~2.8x BW*latency).
// 128-thread blocks give better CTA balance across 148 SMs (7v6 vs 4v3).

#define B_DIM 32
#define T_DIM 128
#define N_DIM 4096
#define THREADS 128
#define TOTAL_THREADS (B_DIM * N_DIM)   // 131072
#define UNROLL 16

__global__ __launch_bounds__(THREADS, 8)
void lif_kernel(const float* __restrict__ x,
                const float* __restrict__ tau_mem,
                const float* __restrict__ vthr,
                float* __restrict__ out)
{
    const int idx = blockIdx.x * THREADS + threadIdx.x;   // 0 .. 131071
    const int n   = idx & (N_DIM - 1);                    // neuron index
    const int b   = idx >> 12;                            // N_DIM == 4096

    const float tau = fminf(fmaxf(tau_mem[n], 0.8f), 0.98f);
    const float omt = 1.0f - tau;
    const float thr = fminf(fmaxf(vthr[n], 0.05f), 0.5f);

    const size_t base = (size_t)b * T_DIM * N_DIM + n;
    const float* __restrict__ xp = x + base;
    float* __restrict__ op = out + base;

    float isyn = 0.f;
    float v    = 0.f;

    // prologue: fill buffer 0 (streaming loads: x is read exactly once)
    float cur[UNROLL];
    #pragma unroll
    for (int u = 0; u < UNROLL; ++u)
        cur[u] = __ldcs(xp + (size_t)u * N_DIM);

    #pragma unroll
    for (int t0 = 0; t0 < T_DIM; t0 += UNROLL) {
        // prefetch next batch FIRST so its loads overlap this batch's compute
        float nxt[UNROLL];
        if (t0 + UNROLL < T_DIM) {
            #pragma unroll
            for (int u = 0; u < UNROLL; ++u)
                nxt[u] = __ldcs(xp + (size_t)(t0 + UNROLL + u) * N_DIM);
        }

        // compute + store current batch (stores interleaved with FMA chain)
        #pragma unroll
        for (int u = 0; u < UNROLL; ++u) {
            isyn = fmaf(0.5f, isyn, cur[u]);
            v    = fmaf(tau, v, __fmul_rn(omt, isyn));
            __stcs(op + (size_t)(t0 + u) * N_DIM, (v >= thr) ? 1.0f : 0.0f);
        }

        if (t0 + UNROLL < T_DIM) {
            #pragma unroll
            for (int u = 0; u < UNROLL; ++u)
                cur[u] = nxt[u];
        }
    }
}

extern "C" void kernel_launch(void* const* d_in, const int* in_sizes, int n_in,
                              void* d_out, int out_size)
{
    const float* x   = (const float*)d_in[0];
    const float* tau = (const float*)d_in[1];
    const float* thr = (const float*)d_in[2];
    float* out = (float*)d_out;

    dim3 grid(TOTAL_THREADS / THREADS);   // 1024 blocks
    dim3 block(THREADS);                  // 128 threads
    lif_kernel<<<grid, block>>>(x, tau, thr, out);
}

// round 8
// speedup vs baseline: 1.3209x; 1.3209x over previous
#include <cuda_runtime.h>
#include <cuda.h>
#include <cuda_bf16.h>
#include <cstdint>

// AssociativeLIF: x (B=32, T=128, N=4096) fp32
//   i_syn[t] = 0.5 * i_syn[t-1] + x[t]
//   v[t]     = tau * v[t-1] + (1 - tau) * i_syn[t]
//   spike[t] = (v[t] >= thr) ? 1.0f : 0.0f
//
// TMA producer/consumer pipeline. Per CTA: 128 neurons of one batch b.
// x tile = 128 t-rows x 512 B (stride 16 KB) -> 3D tensormap, box (128 elem, 16 t).
// 3-stage mbarrier pipeline (24 KB smem), warp 4 produces, warps 0-3 consume.
// In-flight bytes decoupled from registers -> DRAM saturation.

#define B_DIM 32
#define T_DIM 128
#define N_DIM 4096
#define NB_PER_B 32              // 4096 / 128 neurons per CTA
#define STAGE_T 16
#define NSTAGES 3
#define NITERS (T_DIM / STAGE_T) // 8
#define STAGE_BYTES (STAGE_T * 128 * 4)  // 8192
#define CONSUMERS 128
#define THREADS 160              // 4 consumer warps + 1 producer warp

// ---------------- PTX helpers ----------------
__device__ __forceinline__ uint32_t smem_u32(const void* p) {
    uint32_t a;
    asm("{ .reg .u64 t; cvta.to.shared.u64 t, %1; cvt.u32.u64 %0, t; }"
        : "=r"(a) : "l"(p));
    return a;
}

#define MBAR_INIT(addr, cnt) \
    asm volatile("mbarrier.init.shared.b64 [%0], %1;" :: "r"(addr), "r"(cnt) : "memory")

#define MBAR_EXPECT_TX(addr, bytes) \
    asm volatile("mbarrier.arrive.expect_tx.shared.b64 _, [%0], %1;" \
                 :: "r"(addr), "r"(bytes) : "memory")

#define MBAR_ARRIVE(addr) \
    asm volatile("mbarrier.arrive.shared.b64 _, [%0];" :: "r"(addr) : "memory")

#define MBAR_WAIT_ACQ(addr, ph) do {                                          \
    asm volatile(                                                             \
        "{\n\t.reg .pred P;\n\t"                                              \
        "WL_%=:\n\t"                                                          \
        "mbarrier.try_wait.parity.acquire.cta.shared::cta.b64 P, [%0], %1, 0x989680;\n\t" \
        "@P bra.uni WD_%=;\n\t"                                               \
        "bra.uni WL_%=;\n\t"                                                  \
        "WD_%=:\n\t}"                                                         \
        :: "r"(addr), "r"(ph) : "memory");                                    \
} while (0)

#define MBAR_WAIT_RELAXED(addr, ph) do {                                      \
    asm volatile(                                                             \
        "{\n\t.reg .pred P;\n\t"                                              \
        "WL_%=:\n\t"                                                          \
        "mbarrier.try_wait.parity.relaxed.cta.shared::cta.b64 P, [%0], %1, 0x989680;\n\t" \
        "@P bra.uni WD_%=;\n\t"                                               \
        "bra.uni WL_%=;\n\t"                                                  \
        "WD_%=:\n\t}"                                                         \
        :: "r"(addr), "r"(ph) : "memory");                                    \
} while (0)

#define TMA_LOAD_3D(dst, map, cx, cy, cz, mbar)                               \
    asm volatile(                                                             \
        "cp.async.bulk.tensor.3d.shared::cta.global.tile.mbarrier::complete_tx::bytes " \
        "[%0], [%1, {%2, %3, %4}], [%5];"                                     \
        :: "r"(dst), "l"(map), "r"(cx), "r"(cy), "r"(cz), "r"(mbar) : "memory")

// ---------------- kernel ----------------
__global__ __launch_bounds__(THREADS)
void lif_tma_kernel(const __grid_constant__ CUtensorMap tmap,
                    const float* __restrict__ tau_mem,
                    const float* __restrict__ vthr,
                    float* __restrict__ out)
{
    __shared__ __align__(128) float buf[NSTAGES][STAGE_T][128];
    __shared__ __align__(8) unsigned long long full_bar[NSTAGES];
    __shared__ __align__(8) unsigned long long empty_bar[NSTAGES];

    const int tid = threadIdx.x;
    const int b   = blockIdx.x >> 5;            // batch index
    const int nb  = (blockIdx.x & 31) * 128;    // neuron block start

    if (tid == 0) {
        #pragma unroll
        for (int s = 0; s < NSTAGES; ++s) {
            MBAR_INIT(smem_u32(&full_bar[s]), 1);
            MBAR_INIT(smem_u32(&empty_bar[s]), CONSUMERS);
        }
    }
    __syncthreads();

    if (tid == CONSUMERS) {
        // ---- producer (single thread of warp 4) ----
        int slot = 0, phase = 1;   // empty-wait passes immediately on first use
        #pragma unroll 1
        for (int i = 0; i < NITERS; ++i) {
            uint32_t eb = smem_u32(&empty_bar[slot]);
            uint32_t fb = smem_u32(&full_bar[slot]);
            MBAR_WAIT_RELAXED(eb, phase);
            MBAR_EXPECT_TX(fb, STAGE_BYTES);
            TMA_LOAD_3D(smem_u32(&buf[slot][0][0]), &tmap,
                        nb, i * STAGE_T, b, fb);
            if (++slot == NSTAGES) { slot = 0; phase ^= 1; }
        }
    } else if (tid < CONSUMERS) {
        // ---- consumers (warps 0-3, one thread per neuron) ----
        const int n = nb + tid;
        const float tau = fminf(fmaxf(tau_mem[n], 0.8f), 0.98f);
        const float omt = 1.0f - tau;
        const float thr = fminf(fmaxf(vthr[n], 0.05f), 0.5f);

        float* __restrict__ op = out + (size_t)b * T_DIM * N_DIM + n;

        float isyn = 0.f;
        float v    = 0.f;

        int slot = 0, phase = 0;
        #pragma unroll 1
        for (int i = 0; i < NITERS; ++i) {
            uint32_t fb = smem_u32(&full_bar[slot]);
            MBAR_WAIT_ACQ(fb, phase);

            const int t0 = i * STAGE_T;
            #pragma unroll
            for (int tt = 0; tt < STAGE_T; ++tt) {
                float xv = buf[slot][tt][tid];
                isyn = fmaf(0.5f, isyn, xv);
                v    = fmaf(tau, v, __fmul_rn(omt, isyn));
                __stcs(op + (size_t)(t0 + tt) * N_DIM, (v >= thr) ? 1.0f : 0.0f);
            }

            MBAR_ARRIVE(smem_u32(&empty_bar[slot]));
            if (++slot == NSTAGES) { slot = 0; phase ^= 1; }
        }
    }
}

// ---------------- host ----------------
// Hand-rolled typedef: PFN_cuTensorMapEncodeTiled is not exposed by this
// toolkit's cudaTypedefs.h. All argument types come from cuda.h.
typedef CUresult (CUDAAPI *TmaEncodeTiledFn)(
    CUtensorMap* tensorMap, CUtensorMapDataType tensorDataType,
    cuuint32_t tensorRank, void* globalAddress,
    const cuuint64_t* globalDim, const cuuint64_t* globalStrides,
    const cuuint32_t* boxDim, const cuuint32_t* elementStrides,
    CUtensorMapInterleave interleave, CUtensorMapSwizzle swizzle,
    CUtensorMapL2promotion l2Promotion, CUtensorMapFloatOOBfill oobFill);

extern "C" void kernel_launch(void* const* d_in, const int* in_sizes, int n_in,
                              void* d_out, int out_size)
{
    const float* x   = (const float*)d_in[0];
    const float* tau = (const float*)d_in[1];
    const float* thr = (const float*)d_in[2];
    float* out = (float*)d_out;

    // Encode tensormap for x viewed as (B, T, N) fp32:
    //   dim0 = N (4096 elems, contiguous), dim1 = T (stride 16 KB), dim2 = B.
    // Box = (128 elems, STAGE_T rows, 1).
    TmaEncodeTiledFn enc = nullptr;
    {
        void* p = nullptr;
        cudaDriverEntryPointQueryResult qr;
#if CUDART_VERSION >= 12050
        cudaGetDriverEntryPointByVersion("cuTensorMapEncodeTiled", &p, 12000,
                                         cudaEnableDefault, &qr);
#else
        cudaGetDriverEntryPoint("cuTensorMapEncodeTiled", &p,
                                cudaEnableDefault, &qr);
#endif
        enc = (TmaEncodeTiledFn)p;
    }

    CUtensorMap tmap;
    cuuint64_t dims[3]    = {N_DIM, T_DIM, B_DIM};
    cuuint64_t strides[2] = {(cuuint64_t)N_DIM * 4,
                             (cuuint64_t)N_DIM * 4 * T_DIM};
    cuuint32_t box[3]     = {128, STAGE_T, 1};
    cuuint32_t estr[3]    = {1, 1, 1};
    enc(&tmap, CU_TENSOR_MAP_DATA_TYPE_FLOAT32, 3, (void*)x,
        dims, strides, box, estr,
        CU_TENSOR_MAP_INTERLEAVE_NONE, CU_TENSOR_MAP_SWIZZLE_NONE,
        CU_TENSOR_MAP_L2_PROMOTION_L2_128B,
        CU_TENSOR_MAP_FLOAT_OOB_FILL_NONE);

    dim3 grid(B_DIM * NB_PER_B);   // 1024 CTAs
    dim3 block(THREADS);           // 160 threads
    lif_tma_kernel<<<grid, block>>>(tmap, tau, thr, out);
}